// round 4
// baseline (speedup 1.0000x reference)
#include <cuda_runtime.h>

#define HW   16384
#define NB   2
#define CIN  128
#define CO   64
#define NK   64
#define NPIX (NB*HW)

// accumulator pack
#define ACC_SUMS  0        // 8192 floats: [b][k][o]
#define ACC_CNT   8192     // 128 floats:  [b][k]
#define ACC_BNSUM 8320     // 64
#define ACC_BNSQ  8384     // 64
#define ACCN      8448

// ---------------- scratch (static device globals; zero-initialized by loader) ----------------
__device__ float g_xt[(size_t)NPIX*CO];      // [b][hw][o] pixel-major, 8 MB
__device__ float g_acc[ACCN];
__device__ int   g_flag;
__device__ float g_invcov[CO*CO];
__device__ float g_means[NB*NK*CO];
__device__ float g_T[NB*NK*CO];
__device__ float g_diag[NB*NK];
__device__ float g_adjm[NB*NK*CO];

// ---------------- helpers ----------------
__device__ __forceinline__ unsigned long long pk2(float v) {
    unsigned long long r; unsigned u = __float_as_uint(v);
    asm("mov.b64 %0, {%1, %2};" : "=l"(r) : "r"(u), "r"(u));
    return r;
}
__device__ __forceinline__ void ffma2(unsigned long long& d,
                                      unsigned long long a, unsigned long long b) {
    asm("fma.rn.f32x2 %0, %1, %2, %3;" : "=l"(d) : "l"(a), "l"(b), "l"(d));
}
__device__ __forceinline__ void red4(float* p, float a, float b, float c, float d) {
    asm volatile("red.add.v4.f32 [%0], {%1, %2, %3, %4};"
                 :: "l"(p), "f"(a), "f"(b), "f"(c), "f"(d) : "memory");
}
__device__ __forceinline__ void cpa16(float* sdst, const float* gsrc) {
    unsigned saddr = (unsigned)__cvta_generic_to_shared(sdst);
    asm volatile("cp.async.ca.shared.global [%0], [%1], 16;" :: "r"(saddr), "l"(gsrc));
}
__device__ __forceinline__ void cpa_commit() { asm volatile("cp.async.commit_group;"); }
template<int N> __device__ __forceinline__ void cpa_wait() {
    asm volatile("cp.async.wait_group %0;" :: "n"(N));
}
__device__ __forceinline__ int ld_acq(const int* p) {
    int v; asm volatile("ld.acquire.gpu.b32 %0, [%1];" : "=r"(v) : "l"(p) : "memory");
    return v;
}

// ---------------- Kernel 1: GEMM (blocks 0..255, 128px each) + inverse (block 256) ----------------
__global__ __launch_bounds__(256) void k_main(const float* __restrict__ x,
                                              const float* __restrict__ Wft,
                                              const int*   __restrict__ idx,
                                              const float* __restrict__ Wm) {
    __shared__ float sm[8448];
    const int tid = threadIdx.x;

    if (blockIdx.x == 256) {
        // zero BN accumulators + flag for this replay (consumed later this replay)
        if (tid < 128) g_acc[ACC_BNSUM + tid] = 0.f;
        if (tid == 128) g_flag = 0;
        // inv(Wm Wm^T), Gauss-Jordan, SPD
        float* aug  = sm;          // 64 x 128
        float* colp = sm + 8192;   // 64
        float* prow = sm + 8256;   // 128
        for (int e = tid; e < 4096; e += 256) {
            int i = e >> 6, j = e & 63;
            float s = 0.f;
            for (int c = 0; c < 64; c += 4) {
                float4 a  = *(const float4*)(Wm + i*64 + c);
                float4 bb = *(const float4*)(Wm + j*64 + c);
                s += a.x*bb.x + a.y*bb.y + a.z*bb.z + a.w*bb.w;
            }
            aug[i*128 + j]      = s;
            aug[i*128 + 64 + j] = (i == j) ? 1.f : 0.f;
        }
        __syncthreads();
        for (int p = 0; p < 64; p++) {
            if (tid < 64) {
                colp[tid] = aug[tid*128 + p];
            } else if (tid < 192) {
                int j = tid - 64;
                prow[j] = aug[p*128 + j] * (1.f / aug[p*128 + p]);
            }
            __syncthreads();
            for (int e = tid; e < 8192; e += 256) {
                int i = e >> 7, j = e & 127;
                float pr = prow[j];
                aug[e] = (i == p) ? pr : fmaf(-colp[i], pr, aug[e]);
            }
            __syncthreads();
        }
        for (int e = tid; e < 4096; e += 256)
            g_invcov[e] = aug[(e>>6)*128 + 64 + (e&63)];
        return;
    }

    // ---- GEMM: 128 px x 64 out per block, double-buffered cp.async ----
    float* xs   = sm;                 // 2 x 1024
    float* ws   = sm + 2048;          // 2 x 512
    float* scnt = sm + 3072;          // 64
    int*   sidx = (int*)(sm + 3136);  // 128

    const int P0  = blockIdx.x * 128;
    const int b   = P0 >> 14;
    const int hw0 = P0 & (HW-1);
    const float* xb = x + (size_t)b*CIN*HW + hw0;

    if (tid < 64) scnt[tid] = 0.f;
    if (tid < 32) ((int4*)sidx)[tid] = ((const int4*)(idx + P0))[tid];

    const int chg = tid & 7;     // 8 o-groups of 8
    const int pxq = tid >> 3;    // 32 px-groups of 4
    unsigned long long acc2[4][4];
#pragma unroll
    for (int i = 0; i < 4; i++)
#pragma unroll
        for (int j = 0; j < 4; j++) acc2[i][j] = 0ull;

    const int xr = tid >> 5, xc = (tid & 31) * 4;   // 8 rows x 128 px, 1 cpa16/thread
    cpa16(xs + xr*128 + xc, xb + (size_t)xr*HW + xc);
    if (tid < 128) cpa16(ws + tid*4, Wft + tid*4);
    cpa_commit();

    for (int t = 0; t < 16; t++) {
        const int buf = t & 1;
        if (t < 15) {
            cpa16(xs + (buf^1)*1024 + xr*128 + xc,
                  xb + (size_t)((t+1)*8 + xr)*HW + xc);
            if (tid < 128) cpa16(ws + (buf^1)*512 + tid*4, Wft + (t+1)*512 + tid*4);
            cpa_commit();
            cpa_wait<1>();
        } else {
            cpa_wait<0>();
        }
        __syncthreads();
        const float* xsb = xs + buf*1024;
        const float* wsb = ws + buf*512;
#pragma unroll
        for (int cc = 0; cc < 8; cc++) {
            float xv[4];
            *(float4*)xv = *(const float4*)(xsb + cc*128 + pxq*4);
            ulonglong2 wA = *(const ulonglong2*)(wsb + cc*64 + chg*8);
            ulonglong2 wB = *(const ulonglong2*)(wsb + cc*64 + chg*8 + 4);
#pragma unroll
            for (int i = 0; i < 4; i++) {
                unsigned long long ax = pk2(xv[i]);
                ffma2(acc2[i][0], ax, wA.x);
                ffma2(acc2[i][1], ax, wA.y);
                ffma2(acc2[i][2], ax, wB.x);
                ffma2(acc2[i][3], ax, wB.y);
            }
        }
        __syncthreads();
    }

    float* ob = g_xt + ((size_t)b*HW + hw0)*CO;
#pragma unroll
    for (int i = 0; i < 4; i++) {
        int px = pxq*4 + i;
        unsigned long long a0 = acc2[i][0], a1 = acc2[i][1],
                           a2 = acc2[i][2], a3 = acc2[i][3];
        float v0 = __uint_as_float((unsigned)a0), v1 = __uint_as_float((unsigned)(a0>>32));
        float v2 = __uint_as_float((unsigned)a1), v3 = __uint_as_float((unsigned)(a1>>32));
        float v4 = __uint_as_float((unsigned)a2), v5 = __uint_as_float((unsigned)(a2>>32));
        float v6 = __uint_as_float((unsigned)a3), v7 = __uint_as_float((unsigned)(a3>>32));
        *(float4*)(ob + (size_t)px*CO + chg*8)     = make_float4(v0,v1,v2,v3);
        *(float4*)(ob + (size_t)px*CO + chg*8 + 4) = make_float4(v4,v5,v6,v7);
        int k = sidx[px];
        float* sp = g_acc + ACC_SUMS + ((b*NK + k)*CO + chg*8);
        red4(sp,     v0,v1,v2,v3);
        red4(sp + 4, v4,v5,v6,v7);
        if (chg == 0) atomicAdd(&scnt[k], 1.f);
    }
    __syncthreads();
    if (tid < 64) atomicAdd(&g_acc[ACC_CNT + b*64 + tid], scnt[tid]);
}

// ---------------- Kernel 2: means, T = means*invcov, diag ----------------
__global__ __launch_bounds__(256) void k_adjA() {
    __shared__ float As[4096], mR[512], tR[512];
    const int tid = threadIdx.x;
    const int b = blockIdx.x >> 3, r0 = (blockIdx.x & 7) * 8;

    for (int e = tid; e < 1024; e += 256)
        ((float4*)As)[e] = ((const float4*)g_invcov)[e];
    for (int e = tid; e < 512; e += 256) {
        int rl = e >> 6;
        float c = g_acc[ACC_CNT + b*64 + r0 + rl];
        float v = g_acc[ACC_SUMS + b*4096 + r0*64 + e] / ((c > 0.f) ? c : 1.f);
        mR[e] = v;
        g_means[b*4096 + r0*64 + e] = v;
    }
    __syncthreads();
    {
        int il0 = tid >> 6, j = tid & 63, il1 = il0 + 4;
        float a0 = 0.f, a1 = 0.f;
        for (int c = 0; c < 64; c++) {
            float Ac = As[c*64 + j];
            a0 = fmaf(mR[il0*64 + c], Ac, a0);
            a1 = fmaf(mR[il1*64 + c], Ac, a1);
        }
        tR[il0*64 + j] = a0;  tR[il1*64 + j] = a1;
        g_T[b*4096 + (r0+il0)*64 + j] = a0;
        g_T[b*4096 + (r0+il1)*64 + j] = a1;
    }
    __syncthreads();
    if (tid < 8) {
        float d = 0.f;
        for (int c = 0; c < 64; c++)
            d = fmaf(tR[tid*64 + c], mR[tid*64 + c], d);
        g_diag[b*64 + r0 + tid] = d;
    }
}

// ---------------- Kernel 3: G -> adj = exp(-sqrt(q)) -> adjm = adj*means ----------------
__global__ __launch_bounds__(256) void k_adjB() {
    __shared__ float Ms[4096];      // mean[j][c] at Ms[c*64 + (j^(c&31))]
    __shared__ float tRb[512], sadj[512], dg[64];
    const int tid = threadIdx.x;
    const int b = blockIdx.x >> 3, r0 = (blockIdx.x & 7) * 8;

    for (int e = tid; e < 4096; e += 256) {
        int j = e >> 6, c = e & 63;
        Ms[c*64 + (j ^ (c & 31))] = g_means[b*4096 + e];
    }
    for (int e = tid; e < 512; e += 256)
        tRb[e] = g_T[b*4096 + r0*64 + e];
    if (tid < 64) dg[tid] = g_diag[b*64 + tid];
    __syncthreads();
    {
        int il0 = tid >> 6, j = tid & 63, il1 = il0 + 4;
        float a0 = 0.f, a1 = 0.f;
        for (int c = 0; c < 64; c++) {
            float mv = Ms[c*64 + (j ^ (c & 31))];
            a0 = fmaf(tRb[il0*64 + c], mv, a0);
            a1 = fmaf(tRb[il1*64 + c], mv, a1);
        }
        float q0 = dg[r0+il0] + dg[j] - 2.f*a0;
        float q1 = dg[r0+il1] + dg[j] - 2.f*a1;
        sadj[il0*64 + j] = expf(-sqrtf(fmaxf(q0, 1e-12f)));
        sadj[il1*64 + j] = expf(-sqrtf(fmaxf(q1, 1e-12f)));
    }
    __syncthreads();
    {
        int il0 = tid >> 6, o = tid & 63, il1 = il0 + 4;
        float a0 = 0.f, a1 = 0.f;
        for (int jj = 0; jj < 64; jj++) {
            float mv = Ms[o*64 + (jj ^ (o & 31))];
            a0 = fmaf(sadj[il0*64 + jj], mv, a0);
            a1 = fmaf(sadj[il1*64 + jj], mv, a1);
        }
        g_adjm[b*4096 + (r0+il0)*64 + o] = a0;
        g_adjm[b*4096 + (r0+il1)*64 + o] = a1;
    }
}

// ---------------- Kernel 4: persistent fused BN-stats + finalize (grid 128, spin barrier) ----------------
__global__ __launch_bounds__(256) void k_tail(const int* __restrict__ idx,
                                              float* __restrict__ out,
                                              const float* __restrict__ gamma,
                                              const float* __restrict__ beta) {
    __shared__ float am4[4096];     // plain  [k*64 + o]          (phase A float4 reads)
    __shared__ float ams[4096];     // swizzl [k*64 + (o^(k&31))] (phase B scalar reads)
    __shared__ float xts[2112];     // 64 o x 33 (padded) 32-px subtile / phase-A reduction
    __shared__ int   sidx[256];
    __shared__ float ssc[64], sbi[64];
    const int tid = threadIdx.x;
    const int P0  = blockIdx.x * 256;
    const int b   = P0 >> 14;
    const int hw0 = P0 & (HW-1);

    for (int e4 = tid; e4 < 1024; e4 += 256) {
        float4 v = ((const float4*)(g_adjm + b*4096))[e4];
        ((float4*)am4)[e4] = v;
        int flat = e4*4, k = flat >> 6, o = flat & 63, sw = k & 31;
        ams[k*64 + ((o+0)^sw)] = v.x;
        ams[k*64 + ((o+1)^sw)] = v.y;
        ams[k*64 + ((o+2)^sw)] = v.z;
        ams[k*64 + ((o+3)^sw)] = v.w;
    }
    if (tid < 64) ((int4*)sidx)[tid] = ((const int4*)(idx + P0))[tid];
    // re-zero SUMS+CNT for the next replay (already consumed by k_adjA this replay)
    { int e = blockIdx.x*256 + tid; if (e < 8320) g_acc[e] = 0.f; }
    __syncthreads();

    // ---- phase A: BN partial sums over relu(xt + adjm[idx]) ----
    const int pr = tid >> 4, c4 = tid & 15;
    const float4* xb4 = (const float4*)(g_xt + (size_t)P0*CO);
    float4 s4 = make_float4(0,0,0,0), q4 = make_float4(0,0,0,0);
#pragma unroll
    for (int it = 0; it < 16; it++) {
        int px = it*16 + pr;
        int k  = sidx[px];
        float4 xv = xb4[px*16 + c4];
        float4 av = ((float4*)am4)[k*16 + c4];
        float v0 = fmaxf(xv.x+av.x, 0.f), v1 = fmaxf(xv.y+av.y, 0.f);
        float v2 = fmaxf(xv.z+av.z, 0.f), v3 = fmaxf(xv.w+av.w, 0.f);
        s4.x += v0; s4.y += v1; s4.z += v2; s4.w += v3;
        q4.x += v0*v0; q4.y += v1*v1; q4.z += v2*v2; q4.w += v3*v3;
    }
    float* red = xts;
    ((float4*)red)[pr*16 + c4] = s4;
    ((float4*)(red + 1024))[pr*16 + c4] = q4;
    __syncthreads();
    if (tid < 64) {
        float s = 0.f, q = 0.f;
#pragma unroll
        for (int p = 0; p < 16; p++) { s += red[p*64 + tid]; q += red[1024 + p*64 + tid]; }
        atomicAdd(&g_acc[ACC_BNSUM + tid], s);
        atomicAdd(&g_acc[ACC_BNSQ  + tid], q);
    }
    __threadfence();
    __syncthreads();

    // ---- global spin barrier (all 128 blocks resident) ----
    if (tid == 0) {
        atomicAdd(&g_flag, 1);
        while (ld_acq(&g_flag) < 128) __nanosleep(64);
    }
    __syncthreads();

    if (tid < 64) {
        const float invN = 1.f/(float)NPIX;
        float mean = __ldcg(&g_acc[ACC_BNSUM + tid])*invN;
        float var  = __ldcg(&g_acc[ACC_BNSQ  + tid])*invN - mean*mean;
        float s = gamma[tid]*rsqrtf(var + 1e-5f);
        ssc[tid] = s; sbi[tid] = beta[tid] - mean*s;
    }
    __syncthreads();

    // ---- phase B: recompute features, normalize, channel-major write ----
    const int w = tid >> 5, lane = tid & 31;
    float sc8[8], bi8[8];
#pragma unroll
    for (int oo = 0; oo < 8; oo++) { sc8[oo] = ssc[w*8+oo]; bi8[oo] = sbi[w*8+oo]; }

    for (int st = 0; st < 8; st++) {       // 8 subtiles of 32 px
        __syncthreads();
        const float* xbs = g_xt + (size_t)(P0 + st*32)*CO;
        for (int e4 = tid; e4 < 512; e4 += 256) {
            float4 v = ((const float4*)xbs)[e4];
            int flat = e4*4, px = flat >> 6, o = flat & 63;
            xts[(o+0)*33 + px] = v.x;
            xts[(o+1)*33 + px] = v.y;
            xts[(o+2)*33 + px] = v.z;
            xts[(o+3)*33 + px] = v.w;
        }
        __syncthreads();
        int px = lane;
        int k  = sidx[st*32 + px];
        int ksw = k & 31;
        float* ob = out + (size_t)b*CO*HW + hw0 + st*32;
#pragma unroll
        for (int oo = 0; oo < 8; oo++) {
            int o = w*8 + oo;
            float v = xts[o*33 + px] + ams[k*64 + (o ^ ksw)];
            v = fmaxf(v, 0.f);
            ob[(size_t)o*HW + px] = fmaf(v, sc8[oo], bi8[oo]);
        }
    }
}

// ---------------- launch ----------------
extern "C" void kernel_launch(void* const* d_in, const int* in_sizes, int n_in,
                              void* d_out, int out_size) {
    const float* x     = (const float*)d_in[0];
    const int*   index = (const int*)  d_in[1];
    const float* Wft   = (const float*)d_in[2];
    const float* Wm    = (const float*)d_in[3];
    const float* gamma = (const float*)d_in[4];
    const float* beta  = (const float*)d_in[5];
    float* out = (float*)d_out;

    k_main <<<257, 256>>>(x, Wft, index, Wm);
    k_adjA <<<16,  256>>>();
    k_adjB <<<16,  256>>>();
    k_tail <<<128, 256>>>(index, out, gamma, beta);
}

// round 5
// speedup vs baseline: 1.1300x; 1.1300x over previous
#include <cuda_runtime.h>

#define HW   16384
#define NB   2
#define CIN  128
#define CO   64
#define NK   64
#define NPIX (NB*HW)
#define GRIDN 129u

// accumulator pack
#define ACC_SUMS  0        // 8192 floats: [b][k][o]
#define ACC_CNT   8192     // 128 floats:  [b][k]
#define ACC_BNSUM 8320     // 64
#define ACC_BNSQ  8384     // 64
#define ACCN      8448

// ---------------- scratch (static device globals; zero-initialized by loader) ----------------
__device__ float    g_xt[(size_t)NPIX*CO];   // [b][hw][o] pixel-major, 8 MB
__device__ float    g_acc[ACCN];
__device__ unsigned g_bar;                   // monotonic ticket barrier (never reset)
__device__ float    g_invcov[CO*CO];
__device__ float    g_means[NB*NK*CO];
__device__ float    g_T[NB*NK*CO];
__device__ float    g_diag[NB*NK];
__device__ float    g_adjm[NB*NK*CO];

// ---------------- helpers ----------------
__device__ __forceinline__ unsigned long long pk2(float v) {
    unsigned long long r; unsigned u = __float_as_uint(v);
    asm("mov.b64 %0, {%1, %2};" : "=l"(r) : "r"(u), "r"(u));
    return r;
}
__device__ __forceinline__ void ffma2(unsigned long long& d,
                                      unsigned long long a, unsigned long long b) {
    asm("fma.rn.f32x2 %0, %1, %2, %3;" : "=l"(d) : "l"(a), "l"(b), "l"(d));
}
__device__ __forceinline__ void red4(float* p, float a, float b, float c, float d) {
    asm volatile("red.add.v4.f32 [%0], {%1, %2, %3, %4};"
                 :: "l"(p), "f"(a), "f"(b), "f"(c), "f"(d) : "memory");
}
__device__ __forceinline__ void cpa16(float* sdst, const float* gsrc) {
    unsigned saddr = (unsigned)__cvta_generic_to_shared(sdst);
    asm volatile("cp.async.ca.shared.global [%0], [%1], 16;" :: "r"(saddr), "l"(gsrc));
}
__device__ __forceinline__ void cpa_commit() { asm volatile("cp.async.commit_group;"); }
template<int N> __device__ __forceinline__ void cpa_wait() {
    asm volatile("cp.async.wait_group %0;" :: "n"(N));
}

// device-wide ticket barrier; all GRIDN blocks resident, monotonic across replays
__device__ __forceinline__ void gbar() {
    __threadfence();
    __syncthreads();
    if (threadIdx.x == 0) {
        unsigned t   = atomicAdd(&g_bar, 1u);
        unsigned tgt = (t / GRIDN + 1u) * GRIDN;
        unsigned v;
        for (;;) {
            asm volatile("ld.acquire.gpu.u32 %0, [%1];" : "=r"(v) : "l"(&g_bar) : "memory");
            if (v >= tgt) break;
            __nanosleep(32);
        }
    }
    __syncthreads();
}

// ---------------- the single fused kernel ----------------
__global__ __launch_bounds__(256) void k_all(const float* __restrict__ x,
                                             const float* __restrict__ Wft,
                                             const int*   __restrict__ idx,
                                             const float* __restrict__ Wm,
                                             float* __restrict__ out,
                                             const float* __restrict__ gamma,
                                             const float* __restrict__ beta) {
    __shared__ float sm[8448];            // 33 KB union
    int* sidxP = (int*)(sm + 8192);       // persistent sidx region (blocks 0..127)
    const int tid = threadIdx.x;
    const int bx  = blockIdx.x;

    const int P0  = bx * 256;             // pixel tile for blocks 0..127
    const int b   = P0 >> 14;
    const int hw0 = P0 & (HW-1);

    // ================= P0: GEMM (0..127) | inverse (128) =================
    if (bx == 128) {
        if (tid < 128) g_acc[ACC_BNSUM + tid] = 0.f;   // zero BN accums for this replay
        float* aug  = sm;          // 64 x 128
        float* colp = sm + 8192;
        float* prow = sm + 8256;
        for (int e = tid; e < 4096; e += 256) {
            int i = e >> 6, j = e & 63;
            float s = 0.f;
            for (int c = 0; c < 64; c += 4) {
                float4 a  = *(const float4*)(Wm + i*64 + c);
                float4 bb = *(const float4*)(Wm + j*64 + c);
                s += a.x*bb.x + a.y*bb.y + a.z*bb.z + a.w*bb.w;
            }
            aug[i*128 + j]      = s;
            aug[i*128 + 64 + j] = (i == j) ? 1.f : 0.f;
        }
        __syncthreads();
        for (int p = 0; p < 64; p++) {
            if (tid < 64) {
                colp[tid] = aug[tid*128 + p];
            } else if (tid < 192) {
                int j = tid - 64;
                prow[j] = aug[p*128 + j] * (1.f / aug[p*128 + p]);
            }
            __syncthreads();
            for (int e = tid; e < 8192; e += 256) {
                int i = e >> 7, j = e & 127;
                float pr = prow[j];
                aug[e] = (i == p) ? pr : fmaf(-colp[i], pr, aug[e]);
            }
            __syncthreads();
        }
        for (int e = tid; e < 4096; e += 256)
            g_invcov[e] = aug[(e>>6)*128 + 64 + (e&63)];
    } else {
        // ---- GEMM: 256 px x 64 out, 8x8 register tiles, double-buffered cp.async ----
        float* xs   = sm;                 // 2 x 2048
        float* ws   = sm + 4096;          // 2 x 512
        float* scnt = sm + 5120;          // 64

        const float* xb = x + (size_t)b*CIN*HW + hw0;

        if (tid < 64) {
            scnt[tid] = 0.f;
            ((int4*)sidxP)[tid] = ((const int4*)(idx + P0))[tid];
        }

        const int chg = tid & 7;
        const int pxg = tid >> 3;
        unsigned long long acc2[8][4];
#pragma unroll
        for (int i = 0; i < 8; i++)
#pragma unroll
            for (int j = 0; j < 4; j++) acc2[i][j] = 0ull;

        const int r0a = tid >> 6,       c0a = (tid & 63) * 4;
        const int r0b = (tid >> 6) + 4, c0b = c0a;
        {
            cpa16(xs + r0a*256 + c0a, xb + (size_t)r0a*HW + c0a);
            cpa16(xs + r0b*256 + c0b, xb + (size_t)r0b*HW + c0b);
            if (tid < 128) cpa16(ws + tid*4, Wft + tid*4);
            cpa_commit();
        }
        for (int t = 0; t < 16; t++) {
            const int buf = t & 1;
            if (t < 15) {
                float* xd = xs + (buf^1)*2048;
                const float* src = xb + (size_t)(t+1)*8*HW;
                cpa16(xd + r0a*256 + c0a, src + (size_t)r0a*HW + c0a);
                cpa16(xd + r0b*256 + c0b, src + (size_t)r0b*HW + c0b);
                if (tid < 128) cpa16(ws + (buf^1)*512 + tid*4, Wft + (size_t)(t+1)*8*CO + tid*4);
                cpa_commit();
                cpa_wait<1>();
            } else {
                cpa_wait<0>();
            }
            __syncthreads();
            const float* xsb = xs + buf*2048;
            const float* wsb = ws + buf*512;
#pragma unroll
            for (int cc = 0; cc < 8; cc++) {
                float xv[8];
                *(float4*)(xv)   = *(const float4*)(xsb + cc*256 + pxg*8);
                *(float4*)(xv+4) = *(const float4*)(xsb + cc*256 + pxg*8 + 4);
                ulonglong2 wA = *(const ulonglong2*)(wsb + cc*64 + chg*8);
                ulonglong2 wB = *(const ulonglong2*)(wsb + cc*64 + chg*8 + 4);
#pragma unroll
                for (int i = 0; i < 8; i++) {
                    unsigned long long ax = pk2(xv[i]);
                    ffma2(acc2[i][0], ax, wA.x);
                    ffma2(acc2[i][1], ax, wA.y);
                    ffma2(acc2[i][2], ax, wB.x);
                    ffma2(acc2[i][3], ax, wB.y);
                }
            }
            __syncthreads();
        }

        float* ob = g_xt + ((size_t)b*HW + hw0)*CO;
#pragma unroll
        for (int i = 0; i < 8; i++) {
            int px = pxg*8 + i;
            unsigned long long a0 = acc2[i][0], a1 = acc2[i][1],
                               a2 = acc2[i][2], a3 = acc2[i][3];
            float v0 = __uint_as_float((unsigned)a0), v1 = __uint_as_float((unsigned)(a0>>32));
            float v2 = __uint_as_float((unsigned)a1), v3 = __uint_as_float((unsigned)(a1>>32));
            float v4 = __uint_as_float((unsigned)a2), v5 = __uint_as_float((unsigned)(a2>>32));
            float v6 = __uint_as_float((unsigned)a3), v7 = __uint_as_float((unsigned)(a3>>32));
            *(float4*)(ob + (size_t)px*CO + chg*8)     = make_float4(v0,v1,v2,v3);
            *(float4*)(ob + (size_t)px*CO + chg*8 + 4) = make_float4(v4,v5,v6,v7);
            int k = sidxP[px];
            float* sp = g_acc + ACC_SUMS + ((b*NK + k)*CO + chg*8);
            red4(sp,     v0,v1,v2,v3);
            red4(sp + 4, v4,v5,v6,v7);
            if (chg == 0) atomicAdd(&scnt[k], 1.f);
        }
        __syncthreads();
        if (tid < 64) atomicAdd(&g_acc[ACC_CNT + b*64 + tid], scnt[tid]);
    }
    gbar();

    // ================= P1: adjA (blocks 0..15) =================
    if (bx < 16) {
        float* As = sm;            // 4096
        float* mR = sm + 4096;     // 512
        float* tR = sm + 4608;     // 512
        const int ab = bx >> 3, r0 = (bx & 7) * 8;
        for (int e = tid; e < 1024; e += 256)
            ((float4*)As)[e] = ((const float4*)g_invcov)[e];
        for (int e = tid; e < 512; e += 256) {
            int rl = e >> 6;
            float c = g_acc[ACC_CNT + ab*64 + r0 + rl];
            float v = g_acc[ACC_SUMS + ab*4096 + r0*64 + e] / ((c > 0.f) ? c : 1.f);
            mR[e] = v;
            g_means[ab*4096 + r0*64 + e] = v;
        }
        __syncthreads();
        {
            int il0 = tid >> 6, j = tid & 63, il1 = il0 + 4;
            float a0 = 0.f, a1 = 0.f;
            for (int c = 0; c < 64; c++) {
                float Ac = As[c*64 + j];
                a0 = fmaf(mR[il0*64 + c], Ac, a0);
                a1 = fmaf(mR[il1*64 + c], Ac, a1);
            }
            tR[il0*64 + j] = a0;  tR[il1*64 + j] = a1;
            g_T[ab*4096 + (r0+il0)*64 + j] = a0;
            g_T[ab*4096 + (r0+il1)*64 + j] = a1;
        }
        __syncthreads();
        if (tid < 8) {
            float d = 0.f;
            for (int c = 0; c < 64; c++)
                d = fmaf(tR[tid*64 + c], mR[tid*64 + c], d);
            g_diag[ab*64 + r0 + tid] = d;
        }
    }
    gbar();

    // ================= P2: adjB (blocks 0..15) =================
    if (bx < 16) {
        float* Ms   = sm;          // 4096 swizzled means
        float* tRb  = sm + 4096;   // 512
        float* sadj = sm + 4608;   // 512
        float* dg   = sm + 5120;   // 64
        const int ab = bx >> 3, r0 = (bx & 7) * 8;
        for (int e = tid; e < 4096; e += 256) {
            int j = e >> 6, c = e & 63;
            Ms[c*64 + (j ^ (c & 31))] = g_means[ab*4096 + e];
        }
        for (int e = tid; e < 512; e += 256)
            tRb[e] = g_T[ab*4096 + r0*64 + e];
        if (tid < 64) dg[tid] = g_diag[ab*64 + tid];
        __syncthreads();
        {
            int il0 = tid >> 6, j = tid & 63, il1 = il0 + 4;
            float a0 = 0.f, a1 = 0.f;
            for (int c = 0; c < 64; c++) {
                float mv = Ms[c*64 + (j ^ (c & 31))];
                a0 = fmaf(tRb[il0*64 + c], mv, a0);
                a1 = fmaf(tRb[il1*64 + c], mv, a1);
            }
            float q0 = dg[r0+il0] + dg[j] - 2.f*a0;
            float q1 = dg[r0+il1] + dg[j] - 2.f*a1;
            sadj[il0*64 + j] = expf(-sqrtf(fmaxf(q0, 1e-12f)));
            sadj[il1*64 + j] = expf(-sqrtf(fmaxf(q1, 1e-12f)));
        }
        __syncthreads();
        {
            int il0 = tid >> 6, o = tid & 63, il1 = il0 + 4;
            float a0 = 0.f, a1 = 0.f;
            for (int jj = 0; jj < 64; jj++) {
                float mv = Ms[o*64 + (jj ^ (o & 31))];
                a0 = fmaf(sadj[il0*64 + jj], mv, a0);
                a1 = fmaf(sadj[il1*64 + jj], mv, a1);
            }
            g_adjm[ab*4096 + (r0+il0)*64 + o] = a0;
            g_adjm[ab*4096 + (r0+il1)*64 + o] = a1;
        }
    }
    gbar();

    // ================= P3: BN stats (blocks 0..127) + re-zero SUMS/CNT =================
    if (bx < 128) {
        float* am4 = sm;           // 4096
        float* red = sm + 4096;    // 2048
        for (int e4 = tid; e4 < 1024; e4 += 256)
            ((float4*)am4)[e4] = ((const float4*)(g_adjm + b*4096))[e4];
        if (tid < 65) g_acc[bx*65 + tid] = 0.f;     // 128*65 = 8320 = SUMS+CNT
        __syncthreads();

        const int pr = tid >> 4, c4 = tid & 15;
        const float4* xb4 = (const float4*)(g_xt + (size_t)P0*CO);
        float4 s4 = make_float4(0,0,0,0), q4 = make_float4(0,0,0,0);
#pragma unroll
        for (int it = 0; it < 16; it++) {
            int px = it*16 + pr;
            int k  = sidxP[px];
            float4 xv = xb4[px*16 + c4];
            float4 av = ((float4*)am4)[k*16 + c4];
            float v0 = fmaxf(xv.x+av.x, 0.f), v1 = fmaxf(xv.y+av.y, 0.f);
            float v2 = fmaxf(xv.z+av.z, 0.f), v3 = fmaxf(xv.w+av.w, 0.f);
            s4.x += v0; s4.y += v1; s4.z += v2; s4.w += v3;
            q4.x += v0*v0; q4.y += v1*v1; q4.z += v2*v2; q4.w += v3*v3;
        }
        ((float4*)red)[pr*16 + c4] = s4;
        ((float4*)(red + 1024))[pr*16 + c4] = q4;
        __syncthreads();
        if (tid < 64) {
            float s = 0.f, q = 0.f;
#pragma unroll
            for (int p = 0; p < 16; p++) { s += red[p*64 + tid]; q += red[1024 + p*64 + tid]; }
            atomicAdd(&g_acc[ACC_BNSUM + tid], s);
            atomicAdd(&g_acc[ACC_BNSQ  + tid], q);
        }
    }
    gbar();

    // ================= P4: finalize (blocks 0..127) =================
    if (bx < 128) {
        float* ams = sm;           // 4096  [k][o ^ (k&31)]
        float* xts = sm + 4096;    // 2112  [o][px] padded 33
        float* ssc = sm + 6208;    // 64
        float* sbi = sm + 6272;    // 64
        for (int e4 = tid; e4 < 1024; e4 += 256) {
            float4 v = ((const float4*)(g_adjm + b*4096))[e4];
            int flat = e4*4, k = flat >> 6, o = flat & 63, sw = k & 31;
            ams[k*64 + ((o+0)^sw)] = v.x;
            ams[k*64 + ((o+1)^sw)] = v.y;
            ams[k*64 + ((o+2)^sw)] = v.z;
            ams[k*64 + ((o+3)^sw)] = v.w;
        }
        if (tid < 64) {
            const float invN = 1.f/(float)NPIX;
            float mean = __ldcg(&g_acc[ACC_BNSUM + tid])*invN;
            float var  = __ldcg(&g_acc[ACC_BNSQ  + tid])*invN - mean*mean;
            float s = gamma[tid]*rsqrtf(var + 1e-5f);
            ssc[tid] = s; sbi[tid] = beta[tid] - mean*s;
        }
        __syncthreads();

        const int w = tid >> 5, lane = tid & 31;
        float sc8[8], bi8[8];
#pragma unroll
        for (int oo = 0; oo < 8; oo++) { sc8[oo] = ssc[w*8+oo]; bi8[oo] = sbi[w*8+oo]; }

        for (int st = 0; st < 8; st++) {     // 8 subtiles of 32 px
            __syncthreads();
            const float* xbs = g_xt + (size_t)(P0 + st*32)*CO;
            for (int e4 = tid; e4 < 512; e4 += 256) {
                float4 v = ((const float4*)xbs)[e4];
                int flat = e4*4, px = flat >> 6, o = flat & 63;
                xts[(o+0)*33 + px] = v.x;
                xts[(o+1)*33 + px] = v.y;
                xts[(o+2)*33 + px] = v.z;
                xts[(o+3)*33 + px] = v.w;
            }
            __syncthreads();
            int px  = lane;
            int k   = sidxP[st*32 + px];
            int ksw = k & 31;
            float* ob = out + (size_t)b*CO*HW + hw0 + st*32;
#pragma unroll
            for (int oo = 0; oo < 8; oo++) {
                int o = w*8 + oo;
                float v = xts[o*33 + px] + ams[k*64 + (o ^ ksw)];
                v = fmaxf(v, 0.f);
                ob[(size_t)o*HW + px] = fmaf(v, sc8[oo], bi8[oo]);
            }
        }
    }
}

// ---------------- launch ----------------
extern "C" void kernel_launch(void* const* d_in, const int* in_sizes, int n_in,
                              void* d_out, int out_size) {
    const float* x     = (const float*)d_in[0];
    const int*   index = (const int*)  d_in[1];
    const float* Wft   = (const float*)d_in[2];
    const float* Wm    = (const float*)d_in[3];
    const float* gamma = (const float*)d_in[4];
    const float* beta  = (const float*)d_in[5];
    float* out = (float*)d_out;

    k_all<<<GRIDN, 256>>>(x, Wft, index, Wm, out, gamma, beta);
}

// round 7
// speedup vs baseline: 1.3954x; 1.2349x over previous
#include <cuda_runtime.h>

#define HW   16384
#define NB   2
#define CIN  128
#define CO   64
#define NK   64
#define NPIX (NB*HW)
#define GRIDN 129u
#define NT    512

// accumulator pack
#define ACC_SUMS  0        // 8192 floats: [b][k][o]
#define ACC_CNT   8192     // 128 floats:  [b][k]
#define ACC_BNSUM 8320     // 64
#define ACC_BNSQ  8384     // 64
#define ACCN      8448

// ---------------- scratch (static device globals; zero-initialized by loader) ----------------
__device__ float    g_xt[(size_t)NPIX*CO];   // [b][hw][o] pixel-major, 8 MB
__device__ float    g_acc[ACCN];
__device__ unsigned g_bar;                   // monotonic ticket barrier
__device__ float    g_invcov[CO*CO];
__device__ float    g_means[NB*NK*CO];
__device__ float    g_T[NB*NK*CO];
__device__ float    g_diag[NB*NK];
__device__ float    g_adjm[NB*NK*CO];

// ---------------- helpers ----------------
__device__ __forceinline__ unsigned long long pk2(float v) {
    unsigned long long r; unsigned u = __float_as_uint(v);
    asm("mov.b64 %0, {%1, %2};" : "=l"(r) : "r"(u), "r"(u));
    return r;
}
__device__ __forceinline__ void ffma2(unsigned long long& d,
                                      unsigned long long a, unsigned long long b) {
    asm("fma.rn.f32x2 %0, %1, %2, %3;" : "=l"(d) : "l"(a), "l"(b), "l"(d));
}
__device__ __forceinline__ void red4(float* p, float a, float b, float c, float d) {
    asm volatile("red.add.v4.f32 [%0], {%1, %2, %3, %4};"
                 :: "l"(p), "f"(a), "f"(b), "f"(c), "f"(d) : "memory");
}
__device__ __forceinline__ void cpa16(float* sdst, const float* gsrc) {
    unsigned saddr = (unsigned)__cvta_generic_to_shared(sdst);
    asm volatile("cp.async.ca.shared.global [%0], [%1], 16;" :: "r"(saddr), "l"(gsrc));
}
__device__ __forceinline__ void cpa_commit() { asm volatile("cp.async.commit_group;"); }
template<int N> __device__ __forceinline__ void cpa_wait() {
    asm volatile("cp.async.wait_group %0;" :: "n"(N));
}

// device-wide ticket barrier; all GRIDN blocks resident, monotonic across replays
__device__ __forceinline__ void gbar() {
    __threadfence();
    __syncthreads();
    if (threadIdx.x == 0) {
        unsigned t   = atomicAdd(&g_bar, 1u);
        unsigned tgt = (t / GRIDN + 1u) * GRIDN;
        unsigned v;
        for (;;) {
            asm volatile("ld.acquire.gpu.u32 %0, [%1];" : "=r"(v) : "l"(&g_bar) : "memory");
            if (v >= tgt) break;
            __nanosleep(32);
        }
    }
    __syncthreads();
}

// smem layout (floats): GEMM: ws[8192] | xs[2x1024] | scnt[64] | sidxP[256 ints]
#define SMN 10560

// ---------------- the single fused kernel ----------------
__global__ __launch_bounds__(NT) void k_all(const float* __restrict__ x,
                                            const float* __restrict__ Wft,
                                            const int*   __restrict__ idx,
                                            const float* __restrict__ Wm,
                                            float* __restrict__ out,
                                            const float* __restrict__ gamma,
                                            const float* __restrict__ beta) {
    __shared__ float sm[SMN];                  // 41.25 KB union
    int* sidxP = (int*)(sm + 10304);           // persistent across P0/P3/P4
    const int tid = threadIdx.x;
    const int bx  = blockIdx.x;

    const int P0  = bx * 256;                  // pixel tile for blocks 0..127
    const int b   = P0 >> 14;
    const int hw0 = P0 & (HW-1);

    // ================= P0: GEMM (0..127) | inverse (128) =================
    if (bx == 128) {
        if (tid < 128) g_acc[ACC_BNSUM + tid] = 0.f;
        float* aug  = sm;            // 64 x 128
        float* colp = sm + 8192;     // 64
        float* prow = sm + 8256;     // 128
        for (int e = tid; e < 4096; e += NT) {
            int i = e >> 6, j = e & 63;
            float s = 0.f;
            for (int c = 0; c < 64; c += 4) {
                float4 a  = *(const float4*)(Wm + i*64 + c);
                float4 bb = *(const float4*)(Wm + j*64 + c);
                s += a.x*bb.x + a.y*bb.y + a.z*bb.z + a.w*bb.w;
            }
            aug[i*128 + j]      = s;
            aug[i*128 + 64 + j] = (i == j) ? 1.f : 0.f;
        }
        __syncthreads();
        for (int p = 0; p < 64; p++) {
            if (tid < 64) {
                colp[tid] = aug[tid*128 + p];
            } else if (tid < 192) {
                int j = tid - 64;
                prow[j] = aug[p*128 + j] * (1.f / aug[p*128 + p]);
            }
            __syncthreads();
            for (int e = tid; e < 8192; e += NT) {
                int i = e >> 7, j = e & 127;
                float pr = prow[j];
                aug[e] = (i == p) ? pr : fmaf(-colp[i], pr, aug[e]);
            }
            __syncthreads();
        }
        for (int e = tid; e < 4096; e += NT)
            g_invcov[e] = aug[(e>>6)*128 + 64 + (e&63)];
    } else {
        // ---- GEMM: 256 px x 64 out, 512 threads, whole-Wft smem, x dbl-buffered ----
        float* ws   = sm;            // 8192 = full Wft
        float* xs   = sm + 8192;     // 2 x 1024 (4 ch x 256 px)
        float* scnt = sm + 10240;    // 64

        const float* xb = x + (size_t)b*CIN*HW + hw0;

        if (tid < 64) {
            scnt[tid] = 0.f;
            ((int4*)sidxP)[tid] = ((const int4*)(idx + P0))[tid];
        }

        const int chg = tid & 7;     // 8 o-groups of 8
        const int pxq = tid >> 3;    // 64 px-groups of 4
        unsigned long long acc2[4][4];
#pragma unroll
        for (int i = 0; i < 4; i++)
#pragma unroll
            for (int j = 0; j < 4; j++) acc2[i][j] = 0ull;

        // stage whole Wft + first x tile
        for (int e4 = tid; e4 < 2048; e4 += NT)
            cpa16(ws + e4*4, Wft + e4*4);
        const int xr = tid >> 6, xc = (tid & 63) * 4;   // 256 loaders: 4 rows x 256 px
        if (tid < 256) cpa16(xs + xr*256 + xc, xb + (size_t)xr*HW + xc);
        cpa_commit();

        for (int t = 0; t < 32; t++) {                  // 32 tiles of 4 channels
            const int buf = t & 1;
            if (t < 31) {
                if (tid < 256)
                    cpa16(xs + (buf^1)*1024 + xr*256 + xc,
                          xb + (size_t)((t+1)*4 + xr)*HW + xc);
                cpa_commit();
                cpa_wait<1>();
            } else {
                cpa_wait<0>();
            }
            __syncthreads();
            const float* xsb = xs + buf*1024;
#pragma unroll
            for (int cc = 0; cc < 4; cc++) {
                const float* wrow = ws + (t*4 + cc)*64;
                float xv[4];
                *(float4*)xv = *(const float4*)(xsb + cc*256 + pxq*4);
                ulonglong2 wA = *(const ulonglong2*)(wrow + chg*8);
                ulonglong2 wB = *(const ulonglong2*)(wrow + chg*8 + 4);
#pragma unroll
                for (int i = 0; i < 4; i++) {
                    unsigned long long ax = pk2(xv[i]);
                    ffma2(acc2[i][0], ax, wA.x);
                    ffma2(acc2[i][1], ax, wA.y);
                    ffma2(acc2[i][2], ax, wB.x);
                    ffma2(acc2[i][3], ax, wB.y);
                }
            }
            __syncthreads();
        }

        float* ob = g_xt + ((size_t)b*HW + hw0)*CO;
#pragma unroll
        for (int i = 0; i < 4; i++) {
            int px = pxq*4 + i;
            unsigned long long a0 = acc2[i][0], a1 = acc2[i][1],
                               a2 = acc2[i][2], a3 = acc2[i][3];
            float v0 = __uint_as_float((unsigned)a0), v1 = __uint_as_float((unsigned)(a0>>32));
            float v2 = __uint_as_float((unsigned)a1), v3 = __uint_as_float((unsigned)(a1>>32));
            float v4 = __uint_as_float((unsigned)a2), v5 = __uint_as_float((unsigned)(a2>>32));
            float v6 = __uint_as_float((unsigned)a3), v7 = __uint_as_float((unsigned)(a3>>32));
            *(float4*)(ob + (size_t)px*CO + chg*8)     = make_float4(v0,v1,v2,v3);
            *(float4*)(ob + (size_t)px*CO + chg*8 + 4) = make_float4(v4,v5,v6,v7);
            int k = sidxP[px];
            float* sp = g_acc + ACC_SUMS + ((b*NK + k)*CO + chg*8);
            red4(sp,     v0,v1,v2,v3);
            red4(sp + 4, v4,v5,v6,v7);
            if (chg == 0) atomicAdd(&scnt[k], 1.f);
        }
        __syncthreads();
        if (tid < 64) atomicAdd(&g_acc[ACC_CNT + b*64 + tid], scnt[tid]);
    }
    gbar();

    // ================= P1: adjA (blocks 0..15) =================
    if (bx < 16) {
        float* As = sm;            // 4096
        float* mR = sm + 4096;     // 512
        float* tR = sm + 4608;     // 512
        const int ab = bx >> 3, r0 = (bx & 7) * 8;
        for (int e4 = tid; e4 < 1024; e4 += NT)
            ((float4*)As)[e4] = ((const float4*)g_invcov)[e4];
        for (int e = tid; e < 512; e += NT) {
            int rl = e >> 6;
            float c = g_acc[ACC_CNT + ab*64 + r0 + rl];
            float v = g_acc[ACC_SUMS + ab*4096 + r0*64 + e] / ((c > 0.f) ? c : 1.f);
            mR[e] = v;
            g_means[ab*4096 + r0*64 + e] = v;
        }
        __syncthreads();
        {
            int il = tid >> 6, j = tid & 63;          // one (row, col) per thread
            float a = 0.f;
            for (int c = 0; c < 64; c++)
                a = fmaf(mR[il*64 + c], As[c*64 + j], a);
            tR[il*64 + j] = a;
            g_T[ab*4096 + (r0+il)*64 + j] = a;
        }
        __syncthreads();
        if (tid < 8) {
            float d = 0.f;
            for (int c = 0; c < 64; c++)
                d = fmaf(tR[tid*64 + c], mR[tid*64 + c], d);
            g_diag[ab*64 + r0 + tid] = d;
        }
    }
    gbar();

    // ================= P2: adjB (blocks 0..15) =================
    if (bx < 16) {
        float* Ms   = sm;          // 4096 swizzled means [c*64 + (j^(c&31))]
        float* tRb  = sm + 4096;   // 512
        float* sadj = sm + 4608;   // 512
        float* dg   = sm + 5120;   // 64
        const int ab = bx >> 3, r0 = (bx & 7) * 8;
        for (int e = tid; e < 4096; e += NT) {
            int j = e >> 6, c = e & 63;
            Ms[c*64 + (j ^ (c & 31))] = g_means[ab*4096 + e];
        }
        for (int e = tid; e < 512; e += NT)
            tRb[e] = g_T[ab*4096 + r0*64 + e];
        if (tid < 64) dg[tid] = g_diag[ab*64 + tid];
        __syncthreads();
        {
            int il = tid >> 6, j = tid & 63;
            float a = 0.f;
            for (int c = 0; c < 64; c++)
                a = fmaf(tRb[il*64 + c], Ms[c*64 + (j ^ (c & 31))], a);
            float q = dg[r0+il] + dg[j] - 2.f*a;
            sadj[il*64 + j] = expf(-sqrtf(fmaxf(q, 1e-12f)));
        }
        __syncthreads();
        {
            int il = tid >> 6, o = tid & 63;
            float a = 0.f;
            for (int jj = 0; jj < 64; jj++)
                a = fmaf(sadj[il*64 + jj], Ms[o*64 + (jj ^ (o & 31))], a);
            g_adjm[ab*4096 + (r0+il)*64 + o] = a;
        }
    }
    gbar();

    // ================= P3: BN stats (blocks 0..127) + re-zero SUMS/CNT =================
    if (bx < 128) {
        float* am4 = sm;           // 4096
        float* red = sm + 4096;    // 4096: s partials [2048] + q partials [2048]
        for (int e4 = tid; e4 < 1024; e4 += NT)
            ((float4*)am4)[e4] = ((const float4*)(g_adjm + b*4096))[e4];
        if (tid < 65) g_acc[bx*65 + tid] = 0.f;     // 128*65 = 8320 = SUMS+CNT
        __syncthreads();

        const int pr = tid >> 4, c4 = tid & 15;     // 32 px-rows x 16 ch-chunks
        const float4* xb4 = (const float4*)(g_xt + (size_t)P0*CO);
        float4 s4 = make_float4(0,0,0,0), q4 = make_float4(0,0,0,0);
#pragma unroll
        for (int it = 0; it < 8; it++) {
            int px = it*32 + pr;
            int k  = sidxP[px];
            float4 xv = xb4[px*16 + c4];
            float4 av = ((float4*)am4)[k*16 + c4];
            float v0 = fmaxf(xv.x+av.x, 0.f), v1 = fmaxf(xv.y+av.y, 0.f);
            float v2 = fmaxf(xv.z+av.z, 0.f), v3 = fmaxf(xv.w+av.w, 0.f);
            s4.x += v0; s4.y += v1; s4.z += v2; s4.w += v3;
            q4.x += v0*v0; q4.y += v1*v1; q4.z += v2*v2; q4.w += v3*v3;
        }
        ((float4*)red)[pr*16 + c4] = s4;
        ((float4*)(red + 2048))[pr*16 + c4] = q4;
        __syncthreads();
        if (tid < 64) {
            float s = 0.f, q = 0.f;
#pragma unroll
            for (int p = 0; p < 32; p++) { s += red[p*64 + tid]; q += red[2048 + p*64 + tid]; }
            atomicAdd(&g_acc[ACC_BNSUM + tid], s);
            atomicAdd(&g_acc[ACC_BNSQ  + tid], q);
        }
    }
    gbar();

    // ================= P4: finalize (blocks 0..127) =================
    if (bx < 128) {
        float* ams = sm;           // 4096  [k][o ^ (k&31)]
        float* xts = sm + 4096;    // 2112  [o][px] padded 33
        float* ssc = sm + 6208;    // 64
        float* sbi = sm + 6272;    // 64
        for (int e4 = tid; e4 < 1024; e4 += NT) {
            float4 v = ((const float4*)(g_adjm + b*4096))[e4];
            int flat = e4*4, k = flat >> 6, o = flat & 63, sw = k & 31;
            ams[k*64 + ((o+0)^sw)] = v.x;
            ams[k*64 + ((o+1)^sw)] = v.y;
            ams[k*64 + ((o+2)^sw)] = v.z;
            ams[k*64 + ((o+3)^sw)] = v.w;
        }
        if (tid < 64) {
            const float invN = 1.f/(float)NPIX;
            float mean = __ldcg(&g_acc[ACC_BNSUM + tid])*invN;
            float var  = __ldcg(&g_acc[ACC_BNSQ  + tid])*invN - mean*mean;
            float s = gamma[tid]*rsqrtf(var + 1e-5f);
            ssc[tid] = s; sbi[tid] = beta[tid] - mean*s;
        }
        __syncthreads();

        const int w = tid >> 5, lane = tid & 31;    // 16 warps x 4 o each
        float sc4[4], bi4[4];
#pragma unroll
        for (int oo = 0; oo < 4; oo++) { sc4[oo] = ssc[w*4+oo]; bi4[oo] = sbi[w*4+oo]; }

        for (int st = 0; st < 8; st++) {            // 8 subtiles of 32 px
            __syncthreads();
            const float* xbs = g_xt + (size_t)(P0 + st*32)*CO;
            for (int e4 = tid; e4 < 512; e4 += NT) {
                float4 v = ((const float4*)xbs)[e4];
                int flat = e4*4, px = flat >> 6, o = flat & 63;
                xts[(o+0)*33 + px] = v.x;
                xts[(o+1)*33 + px] = v.y;
                xts[(o+2)*33 + px] = v.z;
                xts[(o+3)*33 + px] = v.w;
            }
            __syncthreads();
            int px  = lane;
            int k   = sidxP[st*32 + px];
            int ksw = k & 31;
            float* ob = out + (size_t)b*CO*HW + hw0 + st*32;
#pragma unroll
            for (int oo = 0; oo < 4; oo++) {
                int o = w*4 + oo;
                float v = xts[o*33 + px] + ams[k*64 + (o ^ ksw)];
                v = fmaxf(v, 0.f);
                ob[(size_t)o*HW + px] = fmaf(v, sc4[oo], bi4[oo]);
            }
        }
    }
}

// ---------------- launch ----------------
extern "C" void kernel_launch(void* const* d_in, const int* in_sizes, int n_in,
                              void* d_out, int out_size) {
    const float* x     = (const float*)d_in[0];
    const int*   index = (const int*)  d_in[1];
    const float* Wft   = (const float*)d_in[2];
    const float* Wm    = (const float*)d_in[3];
    const float* gamma = (const float*)d_in[4];
    const float* beta  = (const float*)d_in[5];
    float* out = (float*)d_out;

    k_all<<<GRIDN, NT>>>(x, Wft, index, Wm, out, gamma, beta);
}